// round 16
// baseline (speedup 1.0000x reference)
#include <cuda_runtime.h>
#include <cuda_fp16.h>
#include <cstdint>

#define B_   1024
#define T_   200
#define H_   128
#define G_   384
#define NCTA 128
#define NBT  (B_*T_)

typedef unsigned long long ull;

// mma weights in A-fragment order: m=0 Whh0, 1 Wih1, 2 Whh1, 3 Wih0; [m][tile24][ks8][lane32]
#define WFSZ 6144
__device__ uint4  g_Wf[4*WFSZ];
__device__ uint4  g_WoF[8*8*32];            // h2o frag-packed: [tile8][ks8][lane32]
__device__ float2 g_biasf[40*32];           // loop biases, D-frag order
__device__ float2 g_biasP[24*32];           // pre biases, D-frag order
__device__ float2 g_biasO[8*32];            // h2o biases, D-frag order
// gi0 fp16 D-frags: [bg128][t200][tile24][lane32] half4(ull)
__device__ ull    g_gi0h[(size_t)128*200*24*32];

// ---- helpers ----
__device__ __forceinline__ float sigmoid_fast(float x) {
    return __fdividef(1.0f, 1.0f + __expf(-x));
}
__device__ __forceinline__ float tanh_fast(float x) {
    float ax = fabsf(x);
    float e  = __expf(-2.0f * ax);
    float t  = __fdividef(1.0f - e, 1.0f + e);
    return copysignf(t, x);
}
__device__ __forceinline__ uint32_t h2pk(float a, float b) {
    __half2 h = __floats2half2_rn(a, b);
    return *reinterpret_cast<uint32_t*>(&h);
}
__device__ __forceinline__ float2 pk2f(uint32_t u) {
    __half2 h = *reinterpret_cast<__half2*>(&u);
    return __half22float2(h);
}

// m16n8k16 f16*f16+f32 mma, accumulate into d[4]
__device__ __forceinline__ void mma4(float d[4], uint4 a, uint32_t b0, uint32_t b1)
{
    asm volatile(
        "mma.sync.aligned.m16n8k16.row.col.f32.f16.f16.f32 "
        "{%0,%1,%2,%3},{%4,%5,%6,%7},{%8,%9},{%0,%1,%2,%3};"
        : "+f"(d[0]), "+f"(d[1]), "+f"(d[2]), "+f"(d[3])
        : "r"(a.x), "r"(a.y), "r"(a.z), "r"(a.w), "r"(b0), "r"(b1));
}

// 8-step chain over a tile, weights via LDG, B-frags from registers
__device__ __forceinline__ void chain8(float d[4], const uint4* __restrict__ wp,
                                       const uint32_t* bf)
{
#pragma unroll
    for (int ks = 0; ks < 8; ks++) {
        uint4 a = __ldg(wp + ks * 32);
        mma4(d, a, bf[2*ks], bf[2*ks+1]);
    }
}

// ===================== prep: pack everything =====================
__global__ void prep_kernel(const float* __restrict__ Wih,
                            const float* __restrict__ Whh,
                            const float* __restrict__ bih,
                            const float* __restrict__ bhh,
                            const float* __restrict__ h2o_w,
                            const float* __restrict__ h2o_b)
{
    int idx = blockIdx.x * blockDim.x + threadIdx.x;
    if (idx < 4*WFSZ) {
        int r    = idx % WFSZ;
        int m    = idx / WFSZ;
        int lane = r % 32;
        int ks   = (r / 32) % 8;
        int tile = r / 256;
        const float* W = (m == 0) ? Whh
                       : (m == 1) ? (Wih + (size_t)G_ * H_)
                       : (m == 2) ? (Whh + (size_t)G_ * H_)
                                  : Wih;
        int g = lane >> 2, tg = lane & 3;
        int j0 = tile * 16, k0 = ks * 16;
        uint4 v;
        v.x = h2pk(W[(j0 + g)     * H_ + k0 + tg * 2], W[(j0 + g)     * H_ + k0 + tg * 2 + 1]);
        v.y = h2pk(W[(j0 + g + 8) * H_ + k0 + tg * 2], W[(j0 + g + 8) * H_ + k0 + tg * 2 + 1]);
        v.z = h2pk(W[(j0 + g)     * H_ + k0 + 8 + tg * 2], W[(j0 + g)     * H_ + k0 + 8 + tg * 2 + 1]);
        v.w = h2pk(W[(j0 + g + 8) * H_ + k0 + 8 + tg * 2], W[(j0 + g + 8) * H_ + k0 + 8 + tg * 2 + 1]);
        g_Wf[idx] = v;
    } else if (idx < 4*WFSZ + 2048) {
        int i2   = idx - 4*WFSZ;
        int lane = i2 % 32;
        int ks   = (i2 / 32) % 8;
        int tile = i2 / 256;
        int g = lane >> 2, tg = lane & 3;
        int j0 = tile * 16, k0 = ks * 16;
        uint4 v;
        v.x = h2pk(h2o_w[(j0 + g)     * H_ + k0 + tg * 2], h2o_w[(j0 + g)     * H_ + k0 + tg * 2 + 1]);
        v.y = h2pk(h2o_w[(j0 + g + 8) * H_ + k0 + tg * 2], h2o_w[(j0 + g + 8) * H_ + k0 + tg * 2 + 1]);
        v.z = h2pk(h2o_w[(j0 + g)     * H_ + k0 + 8 + tg * 2], h2o_w[(j0 + g)     * H_ + k0 + 8 + tg * 2 + 1]);
        v.w = h2pk(h2o_w[(j0 + g + 8) * H_ + k0 + 8 + tg * 2], h2o_w[(j0 + g + 8) * H_ + k0 + 8 + tg * 2 + 1]);
        g_WoF[i2] = v;
    } else if (idx < 4*WFSZ + 2048 + 1280) {
        int i3 = idx - 4*WFSZ - 2048;
        int s = i3 / 32, lane = i3 % 32, g = lane >> 2;
        float2 v;
        if (s < 8) {                     // L0 hn: bhh0 n
            int j0 = 256 + s * 16;
            v = make_float2(bhh[j0 + g], bhh[j0 + g + 8]);
        } else if (s < 24) {             // L1 rz: bih1+bhh1
            int j0 = (s - 8) * 16;
            v = make_float2(bih[G_ + j0 + g] + bhh[G_ + j0 + g],
                            bih[G_ + j0 + g + 8] + bhh[G_ + j0 + g + 8]);
        } else if (s < 32) {             // L1 inn: bih1 n
            int j0 = 256 + (s - 24) * 16;
            v = make_float2(bih[G_ + j0 + g], bih[G_ + j0 + g + 8]);
        } else {                         // L1 hn: bhh1 n
            int j0 = 256 + (s - 32) * 16;
            v = make_float2(bhh[G_ + j0 + g], bhh[G_ + j0 + g + 8]);
        }
        g_biasf[i3] = v;
    } else if (idx < 4*WFSZ + 2048 + 1280 + 768) {
        int i4 = idx - 4*WFSZ - 2048 - 1280;
        int s = i4 / 32, lane = i4 % 32, g = lane >> 2;
        float2 v;
        if (s < 16) {                    // L0 rz: bih0+bhh0
            int j0 = s * 16;
            v = make_float2(bih[j0 + g] + bhh[j0 + g],
                            bih[j0 + g + 8] + bhh[j0 + g + 8]);
        } else {                         // L0 inn: bih0 n
            int j0 = 256 + (s - 16) * 16;
            v = make_float2(bih[j0 + g], bih[j0 + g + 8]);
        }
        g_biasP[i4] = v;
    } else if (idx < 4*WFSZ + 2048 + 1280 + 768 + 256) {
        int i5 = idx - 4*WFSZ - 2048 - 1280 - 768;
        int s = i5 / 32, lane = i5 % 32, g = lane >> 2;
        int j0 = s * 16;
        g_biasO[i5] = make_float2(h2o_b[j0 + g], h2o_b[j0 + g + 8]);
    }
}

// ===================== pre-kernel: gi0 via tensor cores + out4-low =====================
// grid = 1024: (bg, t-eighth). 8 warps/block, each strides its own timesteps.
__global__ void __launch_bounds__(256)
pre_kernel(const int* __restrict__ il,
           const float* __restrict__ emb,
           float* __restrict__ out4)
{
    __shared__ uint32_t act[8][512];
    const int tid  = threadIdx.x;
    const int w    = tid >> 5;
    const int lane = tid & 31;
    const int g    = lane >> 2;
    const int tg   = lane & 3;
    const int bg   = blockIdx.x >> 3;
    const int tq   = blockIdx.x & 7;
    const int b0   = bg * 8;

    const uint4* wbase = g_Wf + 3 * WFSZ;
    uint32_t* aw = act[w];
    const int n = lane >> 2;          // row for gather (4 lanes share)

    for (int t = tq * 25 + w; t < tq * 25 + 25; t += 8) {
        int tok = il[(b0 + n) * T_ + t];
        const float4* erow = (const float4*)emb + (size_t)tok * 32;
        float4* o4 = (float4*)(out4 + ((size_t)(b0 + n) * T_ + t) * 256);
#pragma unroll
        for (int i = 0; i < 8; i++) {
            int c = (lane & 3) + 4 * i;        // float4 chunk 0..31
            float4 v = __ldg(erow + c);
            o4[c] = v;
            aw[16 * c + n]     = h2pk(v.x, v.y);
            aw[16 * c + 8 + n] = h2pk(v.z, v.w);
        }
        __syncwarp();

        uint32_t bf[16];
#pragma unroll
        for (int ks = 0; ks < 8; ks++) {
            bf[2*ks]   = aw[(ks * 8 + tg) * 8 + g];
            bf[2*ks+1] = aw[(ks * 8 + tg + 4) * 8 + g];
        }

        ull* gout = g_gi0h + ((size_t)bg * 200 + t) * 24 * 32 + lane;
#pragma unroll 2
        for (int tt = 0; tt < 24; tt++) {
            float2 bv = g_biasP[tt * 32 + lane];
            float d[4] = {bv.x, bv.x, bv.y, bv.y};
            chain8(d, wbase + tt * 256 + lane, bf);
            uint32_t lo = h2pk(d[0], d[1]);
            uint32_t hi = h2pk(d[2], d[3]);
            gout[tt * 32] = (ull)lo | ((ull)hi << 32);
        }
        __syncwarp();
    }
}

// ===================== recurrence loop: fused h2o, 2 barriers/step =====================
__global__ void __launch_bounds__(256, 1)
gru_loop(const float* __restrict__ mask,
         float* __restrict__ out1,
         float* __restrict__ out4)
{
    __shared__ uint32_t h0s[2][512], h1s[2][512], bbs[512], bbh[512];

    const int tid  = threadIdx.x;
    const int w    = tid >> 5;        // warp 0..7: owns hidden cols [16w,16w+16)
    const int lane = tid & 31;
    const int g    = lane >> 2;
    const int tg   = lane & 3;
    const int bg   = blockIdx.x;
    const int b0   = bg * 8;
    const int r0   = tg * 2;

    for (int i = tid; i < 512; i += 256) {
        h0s[0][i] = 0u; h0s[1][i] = 0u;
        h1s[0][i] = 0u; h1s[1][i] = 0u;
    }

    // single weight base; tile offsets are compile-time constants (folded into LDG imm)
    const uint4* wB = g_Wf  + w * 256 + lane;
    const uint4* wO = g_WoF + w * 256 + lane;

    const float2 b0hn = g_biasf[( 0 + w) * 32 + lane];
    const float2 b1r  = g_biasf[( 8 + w) * 32 + lane];
    const float2 b1z  = g_biasf[(16 + w) * 32 + lane];
    const float2 b1n  = g_biasf[(24 + w) * 32 + lane];
    const float2 b1hn = g_biasf[(32 + w) * 32 + lane];
    const float2 bO   = g_biasO[w * 32 + lane];

    const ull* gp = g_gi0h + (size_t)bg * 200 * 24 * 32 + lane;

    // prefetch t=0
    ull grh = __ldg(gp + (      w) * 32);
    ull gzh = __ldg(gp + ( 8 + w) * 32);
    ull gnh = __ldg(gp + (16 + w) * 32);
    float mk0 = (__ldg(mask + (b0 + r0)     * T_) != 0.0f) ? 1.0f : 0.0f;
    float mk1 = (__ldg(mask + (b0 + r0 + 1) * T_) != 0.0f) ? 1.0f : 0.0f;

    float h0reg[4] = {0.f, 0.f, 0.f, 0.f};
    float h1reg[4] = {0.f, 0.f, 0.f, 0.f};

    const int c0 = 16 * w + g;
    const int hx0 = (c0 >> 1) * 16 + r0 * 2 + (c0 & 1);
    const int c1 = c0 + 8;
    const int hx2 = (c1 >> 1) * 16 + r0 * 2 + (c1 & 1);

    __syncthreads();

    for (int t = 0; t < T_; t++) {
        const int p = t & 1, q = p ^ 1;

        // ================= Phase 1: layer 0 + h2o(t-1) =================
        uint32_t hb[16];
        {
            const uint32_t* a0 = h0s[p];
#pragma unroll
            for (int ks = 0; ks < 8; ks++) {
                hb[2*ks]   = a0[(ks * 8 + tg) * 8 + g];
                hb[2*ks+1] = a0[(ks * 8 + tg + 4) * 8 + g];
            }
        }
        float2 fr0 = pk2f((uint32_t)grh), fr1 = pk2f((uint32_t)(grh >> 32));
        float2 fz0 = pk2f((uint32_t)gzh), fz1 = pk2f((uint32_t)(gzh >> 32));
        float2 fn0 = pk2f((uint32_t)gnh), fn1 = pk2f((uint32_t)(gnh >> 32));
        float dr[4] = {fr0.x, fr0.y, fr1.x, fr1.y};
        float dz[4] = {fz0.x, fz0.y, fz1.x, fz1.y};
        float dn[4] = {fn0.x, fn0.y, fn1.x, fn1.y};
        float dhn[4] = {b0hn.x, b0hn.x, b0hn.y, b0hn.y};
        chain8(dr,  wB + 0*256,  hb);
        chain8(dz,  wB + 8*256,  hb);
        chain8(dhn, wB + 16*256, hb);

        // fused h2o for t-1 (unmasked h1 frags in bbh)
        if (t > 0) {
            uint32_t bH[16];
#pragma unroll
            for (int ks = 0; ks < 8; ks++) {
                bH[2*ks]   = bbh[(ks * 8 + tg) * 8 + g];
                bH[2*ks+1] = bbh[(ks * 8 + tg + 4) * 8 + g];
            }
            float dO[4] = {bO.x, bO.x, bO.y, bO.y};
            chain8(dO, wO, bH);
            const int tprev = t - 1;
#pragma unroll
            for (int e = 0; e < 4; e++) {
                float o = tanh_fast(dO[e]);
                int row = r0 + (e & 1);
                int col = 16 * w + g + ((e >> 1) ? 8 : 0);
                size_t gb = (size_t)(b0 + row);
                out4[(gb * T_ + tprev) * 256 + 128 + col] = o;
                out1[(gb * (T_ - 1) + tprev) * 128 + col] = o;   // tprev <= 198 in-loop
            }
        }

        // prefetch next step's gi0 + mask
        ull gr2 = 0, gz2 = 0, gn2 = 0;
        float mkA = 0.f, mkB = 0.f;
        if (t + 1 < T_) {
            gr2 = __ldg(gp + ((t+1)*24 +      w) * 32);
            gz2 = __ldg(gp + ((t+1)*24 +  8 + w) * 32);
            gn2 = __ldg(gp + ((t+1)*24 + 16 + w) * 32);
            mkA = (__ldg(mask + (b0 + r0)     * T_ + t + 1) != 0.0f) ? 1.0f : 0.0f;
            mkB = (__ldg(mask + (b0 + r0 + 1) * T_ + t + 1) != 0.0f) ? 1.0f : 0.0f;
        }

        // pointwise L0 (in registers) + stores
        {
            __half* BB = (__half*)bbs;
            __half* HN = (__half*)h0s[q];
#pragma unroll
            for (int e = 0; e < 4; e++) {
                float rv = sigmoid_fast(dr[e]);
                float zv = sigmoid_fast(dz[e]);
                float nv = tanh_fast(fmaf(rv, dhn[e], dn[e]));
                float h  = fmaf(zv, h0reg[e] - nv, nv);
                float mk = (e & 1) ? mk1 : mk0;
                float hm = h * mk;
                h0reg[e] = hm;
                int hidx = ((e >> 1) ? hx2 : hx0) + (e & 1) * 2;
                BB[hidx] = __float2half_rn(h);
                HN[hidx] = __float2half_rn(hm);
            }
        }
        __syncthreads();                                   // B1

        // ================= Phase 2: layer 1 =================
        uint32_t bf[16], hf[16];
        {
            const uint32_t* ab = bbs;
            const uint32_t* a1 = h1s[p];
#pragma unroll
            for (int ks = 0; ks < 8; ks++) {
                bf[2*ks]   = ab[(ks * 8 + tg) * 8 + g];
                bf[2*ks+1] = ab[(ks * 8 + tg + 4) * 8 + g];
                hf[2*ks]   = a1[(ks * 8 + tg) * 8 + g];
                hf[2*ks+1] = a1[(ks * 8 + tg + 4) * 8 + g];
            }
        }
        float er[4]  = {b1r.x,  b1r.x,  b1r.y,  b1r.y};
        float ez[4]  = {b1z.x,  b1z.x,  b1z.y,  b1z.y};
        float en[4]  = {b1n.x,  b1n.x,  b1n.y,  b1n.y};
        float ehn[4] = {b1hn.x, b1hn.x, b1hn.y, b1hn.y};
        chain8(er,  wB + 24*256, bf);
        chain8(er,  wB + 48*256, hf);
        chain8(ez,  wB + 32*256, bf);
        chain8(ez,  wB + 56*256, hf);
        chain8(en,  wB + 40*256, bf);
        chain8(ehn, wB + 64*256, hf);

        // pointwise L1 + stores (unmasked h1 frags to bbh for fused h2o)
        {
            __half* HN = (__half*)h1s[q];
            __half* BH = (__half*)bbh;
#pragma unroll
            for (int e = 0; e < 4; e++) {
                float rv = sigmoid_fast(er[e]);
                float zv = sigmoid_fast(ez[e]);
                float nv = tanh_fast(fmaf(rv, ehn[e], en[e]));
                float h  = fmaf(zv, h1reg[e] - nv, nv);
                float mk = (e & 1) ? mk1 : mk0;
                float hm = h * mk;
                h1reg[e] = hm;
                int hidx = ((e >> 1) ? hx2 : hx0) + (e & 1) * 2;
                BH[hidx] = __float2half_rn(h);
                HN[hidx] = __float2half_rn(hm);
            }
        }
        grh = gr2; gzh = gz2; gnh = gn2;
        mk0 = mkA; mk1 = mkB;
        __syncthreads();                                   // B2
    }

    // ================= epilogue: h2o for t=199 =================
    {
        uint32_t bH[16];
#pragma unroll
        for (int ks = 0; ks < 8; ks++) {
            bH[2*ks]   = bbh[(ks * 8 + tg) * 8 + g];
            bH[2*ks+1] = bbh[(ks * 8 + tg + 4) * 8 + g];
        }
        float dO[4] = {bO.x, bO.x, bO.y, bO.y};
        chain8(dO, wO, bH);
#pragma unroll
        for (int e = 0; e < 4; e++) {
            float o = tanh_fast(dO[e]);
            int row = r0 + (e & 1);
            int col = 16 * w + g + ((e >> 1) ? 8 : 0);
            size_t gb = (size_t)(b0 + row);
            out4[(gb * T_ + (T_ - 1)) * 256 + 128 + col] = o;
        }
    }
}

// out2/out3 gathers
__global__ void gather_kernel(const int* __restrict__ il,
                              const int* __restrict__ neg,
                              const float4* __restrict__ emb4,
                              float4* __restrict__ out2,
                              float4* __restrict__ out3)
{
    int idx = blockIdx.x * blockDim.x + threadIdx.x;
    const int n4 = B_ * (T_ - 1) * (H_ / 4);
    if (idx >= n4) return;
    int k4 = idx & 31;
    int bt = idx >> 5;
    int b  = bt / (T_ - 1);
    int t  = bt - b * (T_ - 1);
    int p  = il [b * T_ + t + 1];
    int qd = neg[b * T_ + t];
    out2[idx] = __ldg(emb4 + (size_t)p  * 32 + k4);
    out3[idx] = __ldg(emb4 + (size_t)qd * 32 + k4);
}

extern "C" void kernel_launch(void* const* d_in, const int* in_sizes, int n_in,
                              void* d_out, int out_size)
{
    const int*   il    = (const int*)  d_in[0];
    const float* mask  = (const float*)d_in[1];
    const int*   neg   = (const int*)  d_in[2];
    const float* emb   = (const float*)d_in[3];
    const float* Wih   = (const float*)d_in[4];
    const float* Whh   = (const float*)d_in[5];
    const float* bih   = (const float*)d_in[6];
    const float* bhh   = (const float*)d_in[7];
    const float* h2o_w = (const float*)d_in[8];
    const float* h2o_b = (const float*)d_in[9];

    float* out  = (float*)d_out;
    float* out1 = out;
    float* out2 = out1 + (size_t)B_ * (T_ - 1) * H_;
    float* out3 = out2 + (size_t)B_ * (T_ - 1) * H_;
    float* out4 = out3 + (size_t)B_ * (T_ - 1) * H_;

    const int nprep = 4*WFSZ + 2048 + 1280 + 768 + 256;
    prep_kernel<<<(nprep + 255) / 256, 256>>>(Wih, Whh, bih, bhh, h2o_w, h2o_b);

    const int n4 = B_ * (T_ - 1) * (H_ / 4);
    gather_kernel<<<(n4 + 255) / 256, 256>>>(il, neg, (const float4*)emb,
                                             (float4*)out2, (float4*)out3);

    pre_kernel<<<1024, 256>>>(il, emb, out4);

    gru_loop<<<NCTA, 256>>>(mask, out1, out4);
}

// round 17
// speedup vs baseline: 1.0658x; 1.0658x over previous
#include <cuda_runtime.h>
#include <cuda_fp16.h>
#include <cstdint>

#define B_   1024
#define T_   200
#define H_   128
#define G_   384
#define NCTA 128
#define NBT  (B_*T_)

typedef unsigned long long ull;

// mma weights in A-fragment order: m=0 Whh0, 1 Wih1, 2 Whh1, 3 Wih0; [m][tile24][ks8][lane32]
#define WFSZ 6144
__device__ uint4  g_Wf[4*WFSZ];
__device__ uint4  g_WoF[8*8*32];            // h2o frag-packed: [tile8][ks8][lane32]
__device__ float2 g_biasf[40*32];           // loop biases, D-frag order
__device__ float2 g_biasP[24*32];           // pre biases, D-frag order
__device__ float2 g_biasO[8*32];            // h2o biases, D-frag order
// gi0 fp16 D-frags: [bg128][t200][tile24][lane32] half4(ull)
__device__ ull    g_gi0h[(size_t)128*200*24*32];
// h1 fp16 B-frag-packed: [bg128][t200][1024 halves]
__device__ __half g_h1h[(size_t)128*200*1024];

// ---- helpers ----
__device__ __forceinline__ float sigmoid_fast(float x) {
    return __fdividef(1.0f, 1.0f + __expf(-x));
}
__device__ __forceinline__ float tanh_fast(float x) {
    float ax = fabsf(x);
    float e  = __expf(-2.0f * ax);
    float t  = __fdividef(1.0f - e, 1.0f + e);
    return copysignf(t, x);
}
__device__ __forceinline__ uint32_t h2pk(float a, float b) {
    __half2 h = __floats2half2_rn(a, b);
    return *reinterpret_cast<uint32_t*>(&h);
}
__device__ __forceinline__ float2 pk2f(uint32_t u) {
    __half2 h = *reinterpret_cast<__half2*>(&u);
    return __half22float2(h);
}

// m16n8k16 f16*f16+f32 mma, accumulate into d[4]
__device__ __forceinline__ void mma4(float d[4], uint4 a, uint32_t b0, uint32_t b1)
{
    asm volatile(
        "mma.sync.aligned.m16n8k16.row.col.f32.f16.f16.f32 "
        "{%0,%1,%2,%3},{%4,%5,%6,%7},{%8,%9},{%0,%1,%2,%3};"
        : "+f"(d[0]), "+f"(d[1]), "+f"(d[2]), "+f"(d[3])
        : "r"(a.x), "r"(a.y), "r"(a.z), "r"(a.w), "r"(b0), "r"(b1));
}

// 8-step chain over a tile, weights via LDG, B-frags from registers
__device__ __forceinline__ void chain8(float d[4], const uint4* __restrict__ wp,
                                       const uint32_t* bf)
{
#pragma unroll
    for (int ks = 0; ks < 8; ks++) {
        uint4 a = __ldg(wp + ks * 32);
        mma4(d, a, bf[2*ks], bf[2*ks+1]);
    }
}

// ===================== prep: pack everything =====================
__global__ void prep_kernel(const float* __restrict__ Wih,
                            const float* __restrict__ Whh,
                            const float* __restrict__ bih,
                            const float* __restrict__ bhh,
                            const float* __restrict__ h2o_w,
                            const float* __restrict__ h2o_b)
{
    int idx = blockIdx.x * blockDim.x + threadIdx.x;
    if (idx < 4*WFSZ) {
        int r    = idx % WFSZ;
        int m    = idx / WFSZ;
        int lane = r % 32;
        int ks   = (r / 32) % 8;
        int tile = r / 256;
        const float* W = (m == 0) ? Whh
                       : (m == 1) ? (Wih + (size_t)G_ * H_)
                       : (m == 2) ? (Whh + (size_t)G_ * H_)
                                  : Wih;
        int g = lane >> 2, tg = lane & 3;
        int j0 = tile * 16, k0 = ks * 16;
        uint4 v;
        v.x = h2pk(W[(j0 + g)     * H_ + k0 + tg * 2], W[(j0 + g)     * H_ + k0 + tg * 2 + 1]);
        v.y = h2pk(W[(j0 + g + 8) * H_ + k0 + tg * 2], W[(j0 + g + 8) * H_ + k0 + tg * 2 + 1]);
        v.z = h2pk(W[(j0 + g)     * H_ + k0 + 8 + tg * 2], W[(j0 + g)     * H_ + k0 + 8 + tg * 2 + 1]);
        v.w = h2pk(W[(j0 + g + 8) * H_ + k0 + 8 + tg * 2], W[(j0 + g + 8) * H_ + k0 + 8 + tg * 2 + 1]);
        g_Wf[idx] = v;
    } else if (idx < 4*WFSZ + 2048) {
        int i2   = idx - 4*WFSZ;
        int lane = i2 % 32;
        int ks   = (i2 / 32) % 8;
        int tile = i2 / 256;
        int g = lane >> 2, tg = lane & 3;
        int j0 = tile * 16, k0 = ks * 16;
        uint4 v;
        v.x = h2pk(h2o_w[(j0 + g)     * H_ + k0 + tg * 2], h2o_w[(j0 + g)     * H_ + k0 + tg * 2 + 1]);
        v.y = h2pk(h2o_w[(j0 + g + 8) * H_ + k0 + tg * 2], h2o_w[(j0 + g + 8) * H_ + k0 + tg * 2 + 1]);
        v.z = h2pk(h2o_w[(j0 + g)     * H_ + k0 + 8 + tg * 2], h2o_w[(j0 + g)     * H_ + k0 + 8 + tg * 2 + 1]);
        v.w = h2pk(h2o_w[(j0 + g + 8) * H_ + k0 + 8 + tg * 2], h2o_w[(j0 + g + 8) * H_ + k0 + 8 + tg * 2 + 1]);
        g_WoF[i2] = v;
    } else if (idx < 4*WFSZ + 2048 + 1280) {
        int i3 = idx - 4*WFSZ - 2048;
        int s = i3 / 32, lane = i3 % 32, g = lane >> 2;
        float2 v;
        if (s < 8) {                     // L0 hn: bhh0 n
            int j0 = 256 + s * 16;
            v = make_float2(bhh[j0 + g], bhh[j0 + g + 8]);
        } else if (s < 24) {             // L1 rz: bih1+bhh1
            int j0 = (s - 8) * 16;
            v = make_float2(bih[G_ + j0 + g] + bhh[G_ + j0 + g],
                            bih[G_ + j0 + g + 8] + bhh[G_ + j0 + g + 8]);
        } else if (s < 32) {             // L1 inn: bih1 n
            int j0 = 256 + (s - 24) * 16;
            v = make_float2(bih[G_ + j0 + g], bih[G_ + j0 + g + 8]);
        } else {                         // L1 hn: bhh1 n
            int j0 = 256 + (s - 32) * 16;
            v = make_float2(bhh[G_ + j0 + g], bhh[G_ + j0 + g + 8]);
        }
        g_biasf[i3] = v;
    } else if (idx < 4*WFSZ + 2048 + 1280 + 768) {
        int i4 = idx - 4*WFSZ - 2048 - 1280;
        int s = i4 / 32, lane = i4 % 32, g = lane >> 2;
        float2 v;
        if (s < 16) {                    // L0 rz: bih0+bhh0
            int j0 = s * 16;
            v = make_float2(bih[j0 + g] + bhh[j0 + g],
                            bih[j0 + g + 8] + bhh[j0 + g + 8]);
        } else {                         // L0 inn: bih0 n
            int j0 = 256 + (s - 16) * 16;
            v = make_float2(bih[j0 + g], bih[j0 + g + 8]);
        }
        g_biasP[i4] = v;
    } else if (idx < 4*WFSZ + 2048 + 1280 + 768 + 256) {
        int i5 = idx - 4*WFSZ - 2048 - 1280 - 768;
        int s = i5 / 32, lane = i5 % 32, g = lane >> 2;
        int j0 = s * 16;
        g_biasO[i5] = make_float2(h2o_b[j0 + g], h2o_b[j0 + g + 8]);
    }
}

// ===================== pre-kernel: gi0 via tensor cores + out4-low + out2/out3 =====================
// grid = 1024: (bg, t-eighth). 8 warps/block, each strides its own timesteps.
__global__ void __launch_bounds__(256)
pre_kernel(const int* __restrict__ il,
           const int* __restrict__ neg,
           const float* __restrict__ emb,
           float* __restrict__ out2,
           float* __restrict__ out3,
           float* __restrict__ out4)
{
    __shared__ uint32_t act[8][512];
    const int tid  = threadIdx.x;
    const int w    = tid >> 5;
    const int lane = tid & 31;
    const int g    = lane >> 2;
    const int tg   = lane & 3;
    const int bg   = blockIdx.x >> 3;
    const int tq   = blockIdx.x & 7;
    const int b0   = bg * 8;

    const uint4* wbase = g_Wf + 3 * WFSZ;
    uint32_t* aw = act[w];
    const int n = lane >> 2;          // row for gather (4 lanes share)

    for (int t = tq * 25 + w; t < tq * 25 + 25; t += 8) {
        const int bglob = b0 + n;
        int tok = il[bglob * T_ + t];
        const float4* erow = (const float4*)emb + (size_t)tok * 32;
        float4* o4 = (float4*)(out4 + ((size_t)bglob * T_ + t) * 256);
        float4* o2 = (t >= 1)
                   ? (float4*)(out2 + ((size_t)bglob * (T_ - 1) + (t - 1)) * 128)
                   : nullptr;
#pragma unroll
        for (int i = 0; i < 8; i++) {
            int c = (lane & 3) + 4 * i;        // float4 chunk 0..31
            float4 v = __ldg(erow + c);
            o4[c] = v;
            if (o2) o2[c] = v;                 // out2[b][t-1] = emb[il[b,t]]
            aw[16 * c + n]     = h2pk(v.x, v.y);
            aw[16 * c + 8 + n] = h2pk(v.z, v.w);
        }
        // out3[b][t] = emb[neg[b,t]]  (t < 199)
        if (t < T_ - 1) {
            int tk3 = neg[bglob * T_ + t];
            const float4* e3 = (const float4*)emb + (size_t)tk3 * 32;
            float4* o3 = (float4*)(out3 + ((size_t)bglob * (T_ - 1) + t) * 128);
#pragma unroll
            for (int i = 0; i < 8; i++) {
                int c = (lane & 3) + 4 * i;
                o3[c] = __ldg(e3 + c);
            }
        }
        __syncwarp();

        uint32_t bf[16];
#pragma unroll
        for (int ks = 0; ks < 8; ks++) {
            bf[2*ks]   = aw[(ks * 8 + tg) * 8 + g];
            bf[2*ks+1] = aw[(ks * 8 + tg + 4) * 8 + g];
        }

        ull* gout = g_gi0h + ((size_t)bg * 200 + t) * 24 * 32 + lane;
#pragma unroll 2
        for (int tt = 0; tt < 24; tt++) {
            float2 bv = g_biasP[tt * 32 + lane];
            float d[4] = {bv.x, bv.x, bv.y, bv.y};
            chain8(d, wbase + tt * 256 + lane, bf);
            uint32_t lo = h2pk(d[0], d[1]);
            uint32_t hi = h2pk(d[2], d[3]);
            gout[tt * 32] = (ull)lo | ((ull)hi << 32);
        }
        __syncwarp();
    }
}

// ===================== post-kernel: h2o via tensor cores =====================
// grid = 1024: (bg, t-eighth)
__global__ void __launch_bounds__(256)
post_kernel(float* __restrict__ out1,
            float* __restrict__ out4)
{
    const int tid  = threadIdx.x;
    const int w    = tid >> 5;
    const int lane = tid & 31;
    const int g    = lane >> 2;
    const int tg   = lane & 3;
    const int bg   = blockIdx.x >> 3;
    const int tq   = blockIdx.x & 7;
    const int b0   = bg * 8;
    const int r0   = tg * 2;

    for (int t = tq * 25 + w; t < tq * 25 + 25; t += 8) {
        const uint32_t* hp = (const uint32_t*)g_h1h + ((size_t)bg * 200 + t) * 512;
        uint32_t bf[16];
#pragma unroll
        for (int ks = 0; ks < 8; ks++) {
            bf[2*ks]   = __ldg(hp + (ks * 8 + tg) * 8 + g);
            bf[2*ks+1] = __ldg(hp + (ks * 8 + tg + 4) * 8 + g);
        }
#pragma unroll
        for (int tt = 0; tt < 8; tt++) {
            float2 bv = g_biasO[tt * 32 + lane];
            float d[4] = {bv.x, bv.x, bv.y, bv.y};
            chain8(d, g_WoF + tt * 256 + lane, bf);
#pragma unroll
            for (int e = 0; e < 4; e++) {
                float o = tanh_fast(d[e]);
                int row = r0 + (e & 1);
                int col = tt * 16 + g + ((e >> 1) ? 8 : 0);
                size_t gb = (size_t)(b0 + row);
                out4[(gb * T_ + t) * 256 + 128 + col] = o;
                if (t < T_ - 1)
                    out1[(gb * (T_ - 1) + t) * 128 + col] = o;
            }
        }
    }
}

// ===================== recurrence loop: in-register pointwise, 2 barriers/step =====================
__global__ void __launch_bounds__(256, 1)
gru_loop(const float* __restrict__ mask)
{
    __shared__ uint32_t h0s[2][512], h1s[2][512], bbs[512];

    const int tid  = threadIdx.x;
    const int w    = tid >> 5;        // warp 0..7: owns hidden cols [16w,16w+16)
    const int lane = tid & 31;
    const int g    = lane >> 2;
    const int tg   = lane & 3;
    const int bg   = blockIdx.x;
    const int b0   = bg * 8;
    const int r0   = tg * 2;

    for (int i = tid; i < 512; i += 256) {
        h0s[0][i] = 0u; h0s[1][i] = 0u;
        h1s[0][i] = 0u; h1s[1][i] = 0u;
    }

    const uint4* W0r  = g_Wf + (0*24 +      w) * 256 + lane;
    const uint4* W0z  = g_Wf + (0*24 +  8 + w) * 256 + lane;
    const uint4* W0n  = g_Wf + (0*24 + 16 + w) * 256 + lane;
    const uint4* W1ir = g_Wf + (1*24 +      w) * 256 + lane;
    const uint4* W1iz = g_Wf + (1*24 +  8 + w) * 256 + lane;
    const uint4* W1in = g_Wf + (1*24 + 16 + w) * 256 + lane;
    const uint4* W1hr = g_Wf + (2*24 +      w) * 256 + lane;
    const uint4* W1hz = g_Wf + (2*24 +  8 + w) * 256 + lane;
    const uint4* W1hn = g_Wf + (2*24 + 16 + w) * 256 + lane;

    const float2 b0hn = g_biasf[( 0 + w) * 32 + lane];
    const float2 b1r  = g_biasf[( 8 + w) * 32 + lane];
    const float2 b1z  = g_biasf[(16 + w) * 32 + lane];
    const float2 b1n  = g_biasf[(24 + w) * 32 + lane];
    const float2 b1hn = g_biasf[(32 + w) * 32 + lane];

    const ull* gp = g_gi0h + (size_t)bg * 200 * 24 * 32 + lane;

    // prefetch t=0
    ull grh = __ldg(gp + (0*24 +      w) * 32);
    ull gzh = __ldg(gp + (0*24 +  8 + w) * 32);
    ull gnh = __ldg(gp + (0*24 + 16 + w) * 32);
    float mk0 = (__ldg(mask + (b0 + r0)     * T_) != 0.0f) ? 1.0f : 0.0f;
    float mk1 = (__ldg(mask + (b0 + r0 + 1) * T_) != 0.0f) ? 1.0f : 0.0f;

    float h0reg[4] = {0.f, 0.f, 0.f, 0.f};
    float h1reg[4] = {0.f, 0.f, 0.f, 0.f};

    const int c0 = 16 * w + g;
    const int hx0 = (c0 >> 1) * 16 + r0 * 2 + (c0 & 1);
    const int c1 = c0 + 8;
    const int hx2 = (c1 >> 1) * 16 + r0 * 2 + (c1 & 1);

    __half* gh1 = g_h1h + (size_t)bg * 200 * 1024;

    __syncthreads();

    for (int t = 0; t < T_; t++) {
        const int p = t & 1, q = p ^ 1;

        // ================= Phase 1: layer 0 =================
        uint32_t hb[16];
        {
            const uint32_t* a0 = h0s[p];
#pragma unroll
            for (int ks = 0; ks < 8; ks++) {
                hb[2*ks]   = a0[(ks * 8 + tg) * 8 + g];
                hb[2*ks+1] = a0[(ks * 8 + tg + 4) * 8 + g];
            }
        }
        float2 fr0 = pk2f((uint32_t)grh), fr1 = pk2f((uint32_t)(grh >> 32));
        float2 fz0 = pk2f((uint32_t)gzh), fz1 = pk2f((uint32_t)(gzh >> 32));
        float2 fn0 = pk2f((uint32_t)gnh), fn1 = pk2f((uint32_t)(gnh >> 32));
        float dr[4] = {fr0.x, fr0.y, fr1.x, fr1.y};
        float dz[4] = {fz0.x, fz0.y, fz1.x, fz1.y};
        float dn[4] = {fn0.x, fn0.y, fn1.x, fn1.y};
        float dhn[4] = {b0hn.x, b0hn.x, b0hn.y, b0hn.y};
        chain8(dr,  W0r, hb);
        chain8(dz,  W0z, hb);
        chain8(dhn, W0n, hb);

        // prefetch next step's gi0 + mask
        ull gr2 = 0, gz2 = 0, gn2 = 0;
        float mkA = 0.f, mkB = 0.f;
        if (t + 1 < T_) {
            gr2 = __ldg(gp + ((t+1)*24 +      w) * 32);
            gz2 = __ldg(gp + ((t+1)*24 +  8 + w) * 32);
            gn2 = __ldg(gp + ((t+1)*24 + 16 + w) * 32);
            mkA = (__ldg(mask + (b0 + r0)     * T_ + t + 1) != 0.0f) ? 1.0f : 0.0f;
            mkB = (__ldg(mask + (b0 + r0 + 1) * T_ + t + 1) != 0.0f) ? 1.0f : 0.0f;
        }

        // pointwise L0 (in registers) + stores
        {
            __half* BB = (__half*)bbs;
            __half* HN = (__half*)h0s[q];
#pragma unroll
            for (int e = 0; e < 4; e++) {
                float rv = sigmoid_fast(dr[e]);
                float zv = sigmoid_fast(dz[e]);
                float nv = tanh_fast(fmaf(rv, dhn[e], dn[e]));
                float h  = fmaf(zv, h0reg[e] - nv, nv);
                float mk = (e & 1) ? mk1 : mk0;
                float hm = h * mk;
                h0reg[e] = hm;
                int hidx = ((e >> 1) ? hx2 : hx0) + (e & 1) * 2;
                BB[hidx] = __float2half_rn(h);
                HN[hidx] = __float2half_rn(hm);
            }
        }
        __syncthreads();                                   // B1

        // ================= Phase 2: layer 1 =================
        uint32_t bf[16], hf[16];
        {
            const uint32_t* ab = bbs;
            const uint32_t* a1 = h1s[p];
#pragma unroll
            for (int ks = 0; ks < 8; ks++) {
                bf[2*ks]   = ab[(ks * 8 + tg) * 8 + g];
                bf[2*ks+1] = ab[(ks * 8 + tg + 4) * 8 + g];
                hf[2*ks]   = a1[(ks * 8 + tg) * 8 + g];
                hf[2*ks+1] = a1[(ks * 8 + tg + 4) * 8 + g];
            }
        }
        float er[4]  = {b1r.x,  b1r.x,  b1r.y,  b1r.y};
        float ez[4]  = {b1z.x,  b1z.x,  b1z.y,  b1z.y};
        float en[4]  = {b1n.x,  b1n.x,  b1n.y,  b1n.y};
        float ehn[4] = {b1hn.x, b1hn.x, b1hn.y, b1hn.y};
        chain8(er,  W1ir, bf);
        chain8(er,  W1hr, hf);
        chain8(ez,  W1iz, bf);
        chain8(ez,  W1hz, hf);
        chain8(en,  W1in, bf);
        chain8(ehn, W1hn, hf);

        // pointwise L1 + stores (h1 emitted fp16 B-frag-packed)
        {
            __half* HN = (__half*)h1s[q];
            __half* GH = gh1 + (size_t)t * 1024;
#pragma unroll
            for (int e = 0; e < 4; e++) {
                float rv = sigmoid_fast(er[e]);
                float zv = sigmoid_fast(ez[e]);
                float nv = tanh_fast(fmaf(rv, ehn[e], en[e]));
                float h  = fmaf(zv, h1reg[e] - nv, nv);
                float mk = (e & 1) ? mk1 : mk0;
                float hm = h * mk;
                h1reg[e] = hm;
                int hidx = ((e >> 1) ? hx2 : hx0) + (e & 1) * 2;
                __half hh = __float2half_rn(h);
                GH[hidx] = hh;
                HN[hidx] = __float2half_rn(hm);
            }
        }
        grh = gr2; gzh = gz2; gnh = gn2;
        mk0 = mkA; mk1 = mkB;
        __syncthreads();                                   // B2
    }
}

extern "C" void kernel_launch(void* const* d_in, const int* in_sizes, int n_in,
                              void* d_out, int out_size)
{
    const int*   il    = (const int*)  d_in[0];
    const float* mask  = (const float*)d_in[1];
    const int*   neg   = (const int*)  d_in[2];
    const float* emb   = (const float*)d_in[3];
    const float* Wih   = (const float*)d_in[4];
    const float* Whh   = (const float*)d_in[5];
    const float* bih   = (const float*)d_in[6];
    const float* bhh   = (const float*)d_in[7];
    const float* h2o_w = (const float*)d_in[8];
    const float* h2o_b = (const float*)d_in[9];

    float* out  = (float*)d_out;
    float* out1 = out;
    float* out2 = out1 + (size_t)B_ * (T_ - 1) * H_;
    float* out3 = out2 + (size_t)B_ * (T_ - 1) * H_;
    float* out4 = out3 + (size_t)B_ * (T_ - 1) * H_;

    const int nprep = 4*WFSZ + 2048 + 1280 + 768 + 256;
    prep_kernel<<<(nprep + 255) / 256, 256>>>(Wih, Whh, bih, bhh, h2o_w, h2o_b);

    pre_kernel<<<1024, 256>>>(il, neg, emb, out2, out3, out4);

    gru_loop<<<NCTA, 256>>>(mask);

    post_kernel<<<1024, 256>>>(out1, out4);
}